// round 11
// baseline (speedup 1.0000x reference)
#include <cuda_runtime.h>
#include <cuda_bf16.h>
#include <cstdint>

// Shapes:
//   node_emb:    [65536, 64] f32   (d_in[0])
//   feature_emb: [512, 64]   f32   (d_in[1])
//   W:           [1, 128]    f32   (d_in[2])  (w_node = W[0:64], w_feat = W[64:128])
//   b:           [1]         f32   (d_in[3])
//   out[i,j] = node_emb[i,:].w_node + feature_emb[j,:].w_feat + b

#define BS 65536
#define NF 512
#define D  64
#define ROWS_PER_WARP 4

#define NBLOCKS 296                        // 2 per SM on 148-SM B200
#define NTHREADS 512                       // 16 warps/block
#define NWARPS (NBLOCKS * (NTHREADS / 32)) // 4736 warps total
#define NRG (BS / ROWS_PER_WARP)           // 16384 row-groups

// ---------------------------------------------------------------------------
// Single fused kernel.
// Prologue (per block, parallel across blocks): thread t computes
//   feat_s[t] = feature_emb[t,:] . W[64:128] + b      (512 threads = 512 rows)
// feature_emb (128KB) is read by every block but dedups in L2 (38MB L2 reads
// total, negligible vs the 150MB DRAM stream).
// Main loop: grid-strided, 4 rows/warp/iter, software-pipelined node loads,
// 16 independent STG.128 per iter each covering 512 contiguous bytes/warp.
// ---------------------------------------------------------------------------
__global__ __launch_bounds__(NTHREADS, 2) void edge_head_fused(
    const float* __restrict__ node_emb,
    const float* __restrict__ feature_emb,
    const float* __restrict__ W,
    const float* __restrict__ b,
    float* __restrict__ out)
{
    __shared__ float feat_s[NF];

    const int tid  = threadIdx.x;
    const int wid  = tid >> 5;
    const int lane = tid & 31;

    // ---- Prologue: feat projections, thread-per-row ----
    {
        const float4* frow = reinterpret_cast<const float4*>(feature_emb + tid * D);
        const float4* wf   = reinterpret_cast<const float4*>(W + D);   // w_feat
        float acc = 0.0f;
        #pragma unroll
        for (int i = 0; i < D / 4; i++) {
            const float4 a  = frow[i];
            const float4 ww = wf[i];
            acc = fmaf(a.x, ww.x, acc);
            acc = fmaf(a.y, ww.y, acc);
            acc = fmaf(a.z, ww.z, acc);
            acc = fmaf(a.w, ww.w, acc);
        }
        feat_s[tid] = acc + b[0];
    }
    __syncthreads();

    // ---- Hoisted per-warp constants ----
    const float2 w = reinterpret_cast<const float2*>(W)[lane];   // w_node[2*lane..]

    // Per-lane feat values, interleaved so each STG.128 covers 512B contiguous.
    const float4* f4 = reinterpret_cast<const float4*>(feat_s);
    const float4 f0 = f4[      lane];
    const float4 f1 = f4[ 32 + lane];
    const float4 f2 = f4[ 64 + lane];
    const float4 f3 = f4[ 96 + lane];

    const float2* ne = reinterpret_cast<const float2*>(node_emb);
    const int gwarp = blockIdx.x * (NTHREADS / 32) + wid;

    // ---- Software-pipelined streaming loop ----
    // v holds node rows for group g; next group's loads issue before the
    // store burst so their latency hides behind the stores + shfl chain.
    int g = gwarp;
    int row0 = g * ROWS_PER_WARP;
    float2 v0 = ne[(row0 + 0) * 32 + lane];
    float2 v1 = ne[(row0 + 1) * 32 + lane];
    float2 v2 = ne[(row0 + 2) * 32 + lane];
    float2 v3 = ne[(row0 + 3) * 32 + lane];

    while (g < NRG) {
        const int gn = g + NWARPS;

        // Issue next iteration's loads early (uniform branch per warp).
        float2 n0, n1, n2, n3;
        if (gn < NRG) {
            const int nr0 = gn * ROWS_PER_WARP;
            n0 = ne[(nr0 + 0) * 32 + lane];
            n1 = ne[(nr0 + 1) * 32 + lane];
            n2 = ne[(nr0 + 2) * 32 + lane];
            n3 = ne[(nr0 + 3) * 32 + lane];
        }

        // 4 independent butterfly reductions, interleaved per stage.
        float p[ROWS_PER_WARP];
        p[0] = fmaf(v0.x, w.x, v0.y * w.y);
        p[1] = fmaf(v1.x, w.x, v1.y * w.y);
        p[2] = fmaf(v2.x, w.x, v2.y * w.y);
        p[3] = fmaf(v3.x, w.x, v3.y * w.y);
        #pragma unroll
        for (int off = 16; off > 0; off >>= 1) {
            #pragma unroll
            for (int r = 0; r < ROWS_PER_WARP; r++)
                p[r] += __shfl_xor_sync(0xffffffffu, p[r], off);
        }

        float4* o4 = reinterpret_cast<float4*>(out + (size_t)g * ROWS_PER_WARP * NF);
        #pragma unroll
        for (int r = 0; r < ROWS_PER_WARP; r++) {
            const float pr = p[r];
            float4* row = o4 + r * (NF / 4);
            float4 t;
            t.x = f0.x + pr; t.y = f0.y + pr; t.z = f0.z + pr; t.w = f0.w + pr;
            __stcs(row +      lane, t);
            t.x = f1.x + pr; t.y = f1.y + pr; t.z = f1.z + pr; t.w = f1.w + pr;
            __stcs(row + 32 + lane, t);
            t.x = f2.x + pr; t.y = f2.y + pr; t.z = f2.z + pr; t.w = f2.w + pr;
            __stcs(row + 64 + lane, t);
            t.x = f3.x + pr; t.y = f3.y + pr; t.z = f3.z + pr; t.w = f3.w + pr;
            __stcs(row + 96 + lane, t);
        }

        v0 = n0; v1 = n1; v2 = n2; v3 = n3;
        g = gn;
    }
}

// ---------------------------------------------------------------------------
extern "C" void kernel_launch(void* const* d_in, const int* in_sizes, int n_in,
                              void* d_out, int out_size)
{
    const float* node_emb    = (const float*)d_in[0];
    const float* feature_emb = (const float*)d_in[1];
    const float* W           = (const float*)d_in[2];
    const float* b           = (const float*)d_in[3];
    float*       out         = (float*)d_out;

    edge_head_fused<<<NBLOCKS, NTHREADS>>>(node_emb, feature_emb, W, b, out);
}

// round 12
// speedup vs baseline: 1.2608x; 1.2608x over previous
#include <cuda_runtime.h>
#include <cuda_bf16.h>
#include <cstdint>

// Shapes:
//   node_emb:    [65536, 64] f32   (d_in[0])
//   feature_emb: [512, 64]   f32   (d_in[1])
//   W:           [1, 128]    f32   (d_in[2])  (w_node = W[0:64], w_feat = W[64:128])
//   b:           [1]         f32   (d_in[3])
//   out[i,j] = node_emb[i,:].w_node + feature_emb[j,:].w_feat + b

#define BS 65536
#define NF 512
#define D  64
#define RPW 8   // rows per warp

// feat_proj + b scratch (allocation-free rule: __device__ global; L2/L1-resident, 2KB).
__device__ float g_feat[NF];

// ---------------------------------------------------------------------------
// Kernel 1 (tiny): g_feat[j] = feature_emb[j,:] . W[64:128] + b
// warp-per-row, 512 rows -> 64 blocks x 256 threads.
// ---------------------------------------------------------------------------
__global__ __launch_bounds__(256) void feat_kernel(
    const float* __restrict__ feature_emb,
    const float* __restrict__ W,
    const float* __restrict__ b)
{
    const int warp = (blockIdx.x * 256 + threadIdx.x) >> 5;
    const int lane = threadIdx.x & 31;
    if (warp >= NF) return;

    const float2 v = reinterpret_cast<const float2*>(feature_emb)[warp * 32 + lane];
    const float2 w = reinterpret_cast<const float2*>(W)[32 + lane];  // W[64 + 2*lane ..]
    float p = fmaf(v.x, w.x, v.y * w.y);

    #pragma unroll
    for (int off = 16; off > 0; off >>= 1)
        p += __shfl_xor_sync(0xffffffffu, p, off);

    if (lane == 0)
        g_feat[warp] = p + b[0];
}

// ---------------------------------------------------------------------------
// Kernel 2: fused node_proj + broadcast stream. FLAT launch (one-shot per
// warp — R11 proved persistence kills this). Warp handles 8 rows:
//  - 8 independent node-row loads front-batched (MLP=8/warp),
//  - 8 butterfly reductions interleaved per stage,
//  - 32 independent STG.128, each covering 512 contiguous bytes per warp.
// ---------------------------------------------------------------------------
__global__ __launch_bounds__(256) void fused_stream_kernel(
    const float* __restrict__ node_emb,
    const float* __restrict__ W,
    float* __restrict__ out)
{
    const int warp = (blockIdx.x * 256 + threadIdx.x) >> 5;
    const int lane = threadIdx.x & 31;
    const int row0 = warp * RPW;

    // Front-batch all 8 node rows (fully coalesced float2 per lane).
    const float2* ne = reinterpret_cast<const float2*>(node_emb);
    float2 v[RPW];
    #pragma unroll
    for (int r = 0; r < RPW; r++)
        v[r] = ne[(row0 + r) * 32 + lane];
    const float2 w = reinterpret_cast<const float2*>(W)[lane];   // w_node[2*lane..]

    // Per-lane feat values, interleaved so each STG.128 covers 512B contiguous.
    const float4* f4 = reinterpret_cast<const float4*>(g_feat);
    const float4 f0 = f4[      lane];
    const float4 f1 = f4[ 32 + lane];
    const float4 f2 = f4[ 64 + lane];
    const float4 f3 = f4[ 96 + lane];

    // 8 independent butterfly reductions, interleaved per stage for ILP.
    float p[RPW];
    #pragma unroll
    for (int r = 0; r < RPW; r++)
        p[r] = fmaf(v[r].x, w.x, v[r].y * w.y);
    #pragma unroll
    for (int off = 16; off > 0; off >>= 1) {
        #pragma unroll
        for (int r = 0; r < RPW; r++)
            p[r] += __shfl_xor_sync(0xffffffffu, p[r], off);
    }

    float4* o4 = reinterpret_cast<float4*>(out + (size_t)row0 * NF);

    #pragma unroll
    for (int r = 0; r < RPW; r++) {
        const float pr = p[r];
        float4* row = o4 + r * (NF / 4);
        float4 t;
        t.x = f0.x + pr; t.y = f0.y + pr; t.z = f0.z + pr; t.w = f0.w + pr;
        __stcs(row +      lane, t);
        t.x = f1.x + pr; t.y = f1.y + pr; t.z = f1.z + pr; t.w = f1.w + pr;
        __stcs(row + 32 + lane, t);
        t.x = f2.x + pr; t.y = f2.y + pr; t.z = f2.z + pr; t.w = f2.w + pr;
        __stcs(row + 64 + lane, t);
        t.x = f3.x + pr; t.y = f3.y + pr; t.z = f3.z + pr; t.w = f3.w + pr;
        __stcs(row + 96 + lane, t);
    }
}

// ---------------------------------------------------------------------------
extern "C" void kernel_launch(void* const* d_in, const int* in_sizes, int n_in,
                              void* d_out, int out_size)
{
    const float* node_emb    = (const float*)d_in[0];
    const float* feature_emb = (const float*)d_in[1];
    const float* W           = (const float*)d_in[2];
    const float* b           = (const float*)d_in[3];
    float*       out         = (float*)d_out;

    // Kernel 1: 512 warps -> 64 blocks x 256 threads (~1.1us).
    feat_kernel<<<64, 256>>>(feature_emb, W, b);

    // Kernel 2: 65536/8 = 8192 warps -> 1024 blocks x 256 threads (8 warps/blk).
    fused_stream_kernel<<<BS / (8 * RPW), 256>>>(node_emb, W, out);
}